// round 13
// baseline (speedup 1.0000x reference)
#include <cuda_runtime.h>
#include <math.h>

#define E_TOT 65536
#define NRELC 64
#define NSEG  2048      // B*N = 4*512
#define HIDC  768
#define NHEAD 12
#define DHC   64

// ---------------- scratch ----------------
__device__ float g_Q[NSEG * HIDC];
__device__ float g_K[NSEG * HIDC];
__device__ float g_V[NSEG * HIDC];
__device__ float g_logits[E_TOT * NHEAD];
__device__ int   g_relCount[NRELC];
__device__ int   g_relOff[NRELC + 1];
__device__ int   g_relCur[NRELC];
__device__ int   g_segCount[NSEG];
__device__ int   g_segOff[NSEG + 1];
__device__ int   g_segCur[NSEG];
__device__ int   g_relEdges[E_TOT];
__device__ int   g_segEdges[E_TOT];

// generational grid barrier state (monotonic across graph replays)
__device__ unsigned g_ticket;
__device__ unsigned g_release;

#define PREP_BLOCKS 128
#define PREP_THREADS 512

__device__ __forceinline__ void grid_bar() {
    __syncthreads();
    if (threadIdx.x == 0) {
        __threadfence();
        unsigned t = atomicAdd(&g_ticket, 1u);
        unsigned gen = t / PREP_BLOCKS;
        if ((t % PREP_BLOCKS) == PREP_BLOCKS - 1)
            atomicAdd(&g_release, 1u);
        while (*(volatile unsigned*)&g_release <= gen) { }
        __threadfence();
    }
    __syncthreads();
}

// ---------------- helpers ----------------
__device__ __forceinline__ unsigned f2tf32(float x) {
    unsigned u;
    asm("cvt.rna.tf32.f32 %0, %1;" : "=r"(u) : "f"(x));
    return u;
}

__device__ __forceinline__ void mma_tf32(float* d, const unsigned* a, const unsigned* b) {
    asm volatile(
        "mma.sync.aligned.m16n8k8.row.col.f32.tf32.tf32.f32 "
        "{%0,%1,%2,%3},{%4,%5,%6,%7},{%8,%9},{%0,%1,%2,%3};\n"
        : "+f"(d[0]), "+f"(d[1]), "+f"(d[2]), "+f"(d[3])
        : "r"(a[0]), "r"(a[1]), "r"(a[2]), "r"(a[3]), "r"(b[0]), "r"(b[1]));
}

// ---------------- fused prep: zero -> count -> scan -> scatter ----------------
__global__ __launch_bounds__(PREP_THREADS) void prep_kernel(const int* __restrict__ EI)
{
    __shared__ int hrel[NRELC];
    __shared__ int hbase[NRELC];
    __shared__ int sh2[PREP_THREADS];

    int tid = threadIdx.x, bid = blockIdx.x;
    int e = bid * PREP_THREADS + tid;

    if (bid == 0 && tid < NRELC) { g_relCount[tid] = 0; g_relCur[tid] = 0; }
    if (bid < 4) { g_segCount[bid * 512 + tid] = 0; g_segCur[bid * 512 + tid] = 0; }
    grid_bar();

    if (tid < NRELC) hrel[tid] = 0;
    __syncthreads();
    int r = EI[3 * E_TOT + e];
    int s = EI[e] * 512 + EI[E_TOT + e];
    atomicAdd(&hrel[r], 1);
    atomicAdd(&g_segCount[s], 1);
    __syncthreads();
    if (tid < NRELC && hrel[tid] != 0) atomicAdd(&g_relCount[tid], hrel[tid]);
    grid_bar();

    if (bid == 0) {
        int a0 = g_segCount[tid * 4 + 0], a1 = g_segCount[tid * 4 + 1];
        int a2 = g_segCount[tid * 4 + 2], a3 = g_segCount[tid * 4 + 3];
        int sum = a0 + a1 + a2 + a3;
        sh2[tid] = sum;
        __syncthreads();
        for (int off = 1; off < PREP_THREADS; off <<= 1) {
            int v = (tid >= off) ? sh2[tid - off] : 0;
            __syncthreads();
            sh2[tid] += v;
            __syncthreads();
        }
        int excl = sh2[tid] - sum;
        g_segOff[tid * 4 + 0] = excl;
        g_segOff[tid * 4 + 1] = excl + a0;
        g_segOff[tid * 4 + 2] = excl + a0 + a1;
        g_segOff[tid * 4 + 3] = excl + a0 + a1 + a2;
        if (tid == PREP_THREADS - 1) g_segOff[NSEG] = sh2[tid];
        if (tid == 0) {
            int acc = 0;
            for (int i = 0; i < NRELC; i++) { g_relOff[i] = acc; acc += g_relCount[i]; }
            g_relOff[NRELC] = acc;
        }
    }
    grid_bar();

    if (tid < NRELC) hrel[tid] = 0;
    __syncthreads();
    int lrank = atomicAdd(&hrel[r], 1);
    __syncthreads();
    if (tid < NRELC) {
        int c = hrel[tid];
        hbase[tid] = c ? atomicAdd(&g_relCur[tid], c) : 0;
    }
    __syncthreads();
    g_relEdges[g_relOff[r] + hbase[r] + lrank] = e;
    int q = atomicAdd(&g_segCur[s], 1);
    g_segEdges[g_segOff[s] + q] = e;
}

// ---------------- QKV GEMM via tf32 tensor MMA (R9 winner: 128x64 tile) ----------------
__global__ __launch_bounds__(256) void qkv_gemm_tc(
    const float* __restrict__ X,
    const float* __restrict__ Wq, const float* __restrict__ bq,
    const float* __restrict__ Wk, const float* __restrict__ bk,
    const float* __restrict__ Wv, const float* __restrict__ bv)
{
    const float* W; const float* bias; float* out;
    if (blockIdx.z == 0)      { W = Wq; bias = bq; out = g_Q; }
    else if (blockIdx.z == 1) { W = Wk; bias = bk; out = g_K; }
    else                      { W = Wv; bias = bv; out = g_V; }

    __shared__ unsigned As[32 * 132];
    __shared__ unsigned Bs[32 * 68];

    int tid = threadIdx.x;
    int lane = tid & 31, w = tid >> 5;
    int wm = w >> 1, wn = w & 1;
    int m0 = blockIdx.x * 128, n0 = blockIdx.y * 64;

    float acc[2][4][4];
#pragma unroll
    for (int i = 0; i < 2; i++)
#pragma unroll
        for (int j = 0; j < 4; j++)
#pragma unroll
            for (int k = 0; k < 4; k++) acc[i][j][k] = 0.f;

    float4 aR[4], bR[2];

#pragma unroll
    for (int j = 0; j < 4; j++) {
        int f4 = tid + j * 256;
        int row = f4 >> 3, c = f4 & 7;
        aR[j] = *(const float4*)&X[(m0 + row) * HIDC + c * 4];
    }
#pragma unroll
    for (int j = 0; j < 2; j++) {
        int f4 = tid + j * 256;
        int n = f4 >> 3, c = f4 & 7;
        bR[j] = *(const float4*)&W[(n0 + n) * HIDC + c * 4];
    }

    for (int kc = 0; kc < 24; kc++) {
#pragma unroll
        for (int j = 0; j < 4; j++) {
            int f4 = tid + j * 256;
            int row = f4 >> 3, c = f4 & 7;
            int sm = (row >> 4) * 4 + (c >> 1);
            unsigned* p = &As[(sm * 33 + (c & 1) * 16 + (row & 15)) * 4];
            *(uint4*)p = make_uint4(f2tf32(aR[j].x), f2tf32(aR[j].y),
                                    f2tf32(aR[j].z), f2tf32(aR[j].w));
        }
#pragma unroll
        for (int j = 0; j < 2; j++) {
            int f4 = tid + j * 256;
            int n = f4 >> 3, c = f4 & 7;
            int sub = (n >> 3) * 4 + (c >> 1);
            unsigned* p = &Bs[(sub * 17 + (c & 1) * 8 + (n & 7)) * 4];
            *(uint4*)p = make_uint4(f2tf32(bR[j].x), f2tf32(bR[j].y),
                                    f2tf32(bR[j].z), f2tf32(bR[j].w));
        }
        __syncthreads();

        if (kc < 23) {
            int k0 = (kc + 1) * 32;
#pragma unroll
            for (int j = 0; j < 4; j++) {
                int f4 = tid + j * 256;
                int row = f4 >> 3, c = f4 & 7;
                aR[j] = *(const float4*)&X[(m0 + row) * HIDC + k0 + c * 4];
            }
#pragma unroll
            for (int j = 0; j < 2; j++) {
                int f4 = tid + j * 256;
                int n = f4 >> 3, c = f4 & 7;
                bR[j] = *(const float4*)&W[(n0 + n) * HIDC + k0 + c * 4];
            }
        }

#pragma unroll
        for (int ks = 0; ks < 4; ks++) {
            unsigned af[2][4];
#pragma unroll
            for (int mi = 0; mi < 2; mi++) {
                int ab = ((wm * 2 + mi) * 4 + ks) * 132 + lane;
                af[mi][0] = As[ab];      af[mi][1] = As[ab + 32];
                af[mi][2] = As[ab + 64]; af[mi][3] = As[ab + 96];
            }
#pragma unroll
            for (int nt = 0; nt < 4; nt++) {
                unsigned bf[2];
                int bb = ((wn * 4 + nt) * 4 + ks) * 68 + lane;
                bf[0] = Bs[bb]; bf[1] = Bs[bb + 32];
#pragma unroll
                for (int mi = 0; mi < 2; mi++)
                    mma_tf32(acc[mi][nt], af[mi], bf);
            }
        }
        __syncthreads();
    }

    int g = lane >> 2, t = lane & 3;
#pragma unroll
    for (int mi = 0; mi < 2; mi++) {
        int r0 = m0 + wm * 32 + mi * 16 + g;
#pragma unroll
        for (int nt = 0; nt < 4; nt++) {
            int col = n0 + wn * 32 + nt * 8 + t * 2;
            float b0 = __ldg(&bias[col]), b1 = __ldg(&bias[col + 1]);
            float2 v0 = make_float2(acc[mi][nt][0] + b0, acc[mi][nt][1] + b1);
            *(float2*)&out[r0 * HIDC + col] = v0;
            float2 v1 = make_float2(acc[mi][nt][2] + b0, acc[mi][nt][3] + b1);
            *(float2*)&out[(r0 + 8) * HIDC + col] = v1;
        }
    }
}

// ---------------- edge logits via tf32 MMA (R9 winner: LTE=8, K direct from L2) ----------------
#define LTE 8
#define LOG_NCH 32
#define QS_FLOATS (48 * 132)               // 6336
#define RS_FLOATS (64 * 68)                // 4352
#define LOG_SMEM ((QS_FLOATS + RS_FLOATS) * 4)

__global__ __launch_bounds__(192) void logits_mma(
    const float* __restrict__ rel_emb, const int* __restrict__ EI)
{
    extern __shared__ float smx[];
    unsigned* Qs = (unsigned*)smx;
    unsigned* Rs = (unsigned*)(smx + QS_FLOATS);
    __shared__ int eids[LTE], qrow[LTE], krow[LTE];

    int r = blockIdx.x;
    int cnt = g_relCount[r];
    if ((int)(blockIdx.y * LTE) >= cnt) return;
    int base = g_relOff[r];
    int tid = threadIdx.x, lane = tid & 31, w = tid >> 5;

    // stage R once: fragment-major tf32 (B-operand layout)
    const float* Rg = rel_emb + r * 4096;
    for (int idx = tid; idx < 1024; idx += 192) {
        float4 v = *(const float4*)&Rg[idx * 4];
        int d = idx >> 4, kc0 = (idx & 15) * 4;
        int sub = (d >> 3) * 8 + (kc0 >> 3);
        int p0 = sub * 68 + ((d & 7) >> 2) * 32 + (d & 3);
        int nb = kc0 & 7;
        Rs[p0 + (nb + 0) * 4] = f2tf32(v.x);
        Rs[p0 + (nb + 1) * 4] = f2tf32(v.y);
        Rs[p0 + (nb + 2) * 4] = f2tf32(v.z);
        Rs[p0 + (nb + 3) * 4] = f2tf32(v.w);
    }

    int g = lane >> 2, t = lane & 3;
    int m0r = w * 16 + g, m1r = m0r + 8;
    int i0 = m0r / 12, h0 = m0r - i0 * 12;
    int i1 = m1r / 12, h1 = m1r - i1 * 12;

    for (int c = blockIdx.y * LTE; c < cnt; c += LOG_NCH * LTE) {
        __syncthreads();
        if (tid < LTE) {
            int il = min(c + tid, cnt - 1);
            int e = g_relEdges[base + il];
            eids[tid] = e;
            qrow[tid] = (EI[e] * 512 + EI[E_TOT + e]) * HIDC;
            krow[tid] = (EI[e] * 512 + EI[2 * E_TOT + e]) * HIDC;
        }
        __syncthreads();

        // stage Q (fragment-major tf32): 1536 float4, 8 per thread
#pragma unroll
        for (int j = 0; j < 8; j++) {
            int f4 = tid + j * 192;
            int m = f4 >> 4, dc = f4 & 15;
            int i = m / 12, h = m - i * 12;
            float4 v = *(const float4*)&g_Q[qrow[i] + h * 64 + dc * 4];
            int sm = (m >> 4) * 8 + (dc >> 1);
            unsigned* p = &Qs[(sm * 33 + (dc & 1) * 16 + (m & 15)) * 4];
            *(uint4*)p = make_uint4(f2tf32(v.x), f2tf32(v.y), f2tf32(v.z), f2tf32(v.w));
        }
        __syncthreads();

        // MMA: warp w owns m-tile w (16 rows x 64 cols)
        float acc[8][4];
#pragma unroll
        for (int nt = 0; nt < 8; nt++)
#pragma unroll
            for (int k = 0; k < 4; k++) acc[nt][k] = 0.f;

#pragma unroll
        for (int ks = 0; ks < 8; ks++) {
            unsigned af[4];
            int ab = (w * 8 + ks) * 132 + lane;
            af[0] = Qs[ab];      af[1] = Qs[ab + 32];
            af[2] = Qs[ab + 64]; af[3] = Qs[ab + 96];
#pragma unroll
            for (int nt = 0; nt < 8; nt++) {
                unsigned bf[2];
                int bb = (ks * 8 + nt) * 68 + lane;
                bf[0] = Rs[bb]; bf[1] = Rs[bb + 32];
                mma_tf32(acc[nt], af, bf);
            }
        }

        // epilogue: dot Qp rows with K rows straight from L2
        float p0 = 0.f, p1 = 0.f;
        const float* k0p = &g_K[krow[i0] + h0 * 64];
        const float* k1p = &g_K[krow[i1] + h1 * 64];
#pragma unroll
        for (int nt = 0; nt < 8; nt++) {
            int col = nt * 8 + t * 2;
            float2 ka = *(const float2*)&k0p[col];
            float2 kb = *(const float2*)&k1p[col];
            p0 += acc[nt][0] * ka.x + acc[nt][1] * ka.y;
            p1 += acc[nt][2] * kb.x + acc[nt][3] * kb.y;
        }
        p0 += __shfl_xor_sync(0xffffffffu, p0, 1);
        p0 += __shfl_xor_sync(0xffffffffu, p0, 2);
        p1 += __shfl_xor_sync(0xffffffffu, p1, 1);
        p1 += __shfl_xor_sync(0xffffffffu, p1, 2);
        if (t == 0) {
            if (c + i0 < cnt) g_logits[eids[i0] * NHEAD + h0] = p0 * 0.125f;
            if (c + i1 < cnt) g_logits[eids[i1] * NHEAD + h1] = p1 * 0.125f;
        }
    }
}

// ---------------- per-segment softmax + V aggregation (float4 lanes, R11 measured winner) ----------------
#define AGG_CAP 128
__global__ __launch_bounds__(192) void agg_kernel(
    const int* __restrict__ EI, float* __restrict__ out)
{
    __shared__ float lg[AGG_CAP * 13];
    __shared__ int   tnb2[AGG_CAP];
    __shared__ float shm[NHEAD], shinv[NHEAD];
    __shared__ float ps[32 * NHEAD];
    __shared__ int   tnb[32];

    int s = blockIdx.x;
    int base = g_segOff[s];
    int cnt  = g_segOff[s + 1] - base;
    int tid = threadIdx.x, lane = tid & 31, w = tid >> 5;
    int bb = s >> 9;
    int col = tid * 4;        // 192 threads x 4 floats = 768
    int h0 = tid >> 4;        // col >> 6

    float4 acc = make_float4(0.f, 0.f, 0.f, 0.f);

    if (cnt == 0) {
        *(float4*)&out[s * HIDC + col] = acc;
        return;
    }

    if (cnt <= AGG_CAP) {
        for (int idx = tid; idx < cnt * NHEAD; idx += 192) {
            int j = idx / NHEAD, h = idx - NHEAD * j;
            int e = g_segEdges[base + j];
            lg[j * 13 + h] = g_logits[e * NHEAD + h];
            if (h == 0) tnb2[j] = EI[2 * E_TOT + e];
        }
        __syncthreads();
        for (int h = w; h < NHEAD; h += 6) {
            float m = -1e30f;
            for (int i = lane; i < cnt; i += 32) m = fmaxf(m, lg[i * 13 + h]);
#pragma unroll
            for (int off = 16; off; off >>= 1)
                m = fmaxf(m, __shfl_xor_sync(0xffffffffu, m, off));
            float ss = 0.f;
            for (int i = lane; i < cnt; i += 32) ss += __expf(lg[i * 13 + h] - m);
#pragma unroll
            for (int off = 16; off; off >>= 1)
                ss += __shfl_xor_sync(0xffffffffu, ss, off);
            if (lane == 0) { shm[h] = m; shinv[h] = 1.0f / ss; }
        }
        __syncthreads();
        for (int idx = tid; idx < cnt * NHEAD; idx += 192) {
            int j = idx / NHEAD, h = idx - NHEAD * j;
            lg[j * 13 + h] = __expf(lg[j * 13 + h] - shm[h]) * shinv[h];
        }
        __syncthreads();
        int j = 0;
        for (; j + 4 <= cnt; j += 4) {
            float p0 = lg[(j + 0) * 13 + h0];
            float p1 = lg[(j + 1) * 13 + h0];
            float p2 = lg[(j + 2) * 13 + h0];
            float p3 = lg[(j + 3) * 13 + h0];
            float4 v0 = *(const float4*)&g_V[(bb * 512 + tnb2[j + 0]) * HIDC + col];
            float4 v1 = *(const float4*)&g_V[(bb * 512 + tnb2[j + 1]) * HIDC + col];
            float4 v2 = *(const float4*)&g_V[(bb * 512 + tnb2[j + 2]) * HIDC + col];
            float4 v3 = *(const float4*)&g_V[(bb * 512 + tnb2[j + 3]) * HIDC + col];
            acc.x += p0 * v0.x + p1 * v1.x + p2 * v2.x + p3 * v3.x;
            acc.y += p0 * v0.y + p1 * v1.y + p2 * v2.y + p3 * v3.y;
            acc.z += p0 * v0.z + p1 * v1.z + p2 * v2.z + p3 * v3.z;
            acc.w += p0 * v0.w + p1 * v1.w + p2 * v2.w + p3 * v3.w;
        }
        for (; j < cnt; j++) {
            float p = lg[j * 13 + h0];
            float4 v = *(const float4*)&g_V[(bb * 512 + tnb2[j]) * HIDC + col];
            acc.x += p * v.x; acc.y += p * v.y; acc.z += p * v.z; acc.w += p * v.w;
        }
    } else {
        // streaming fallback
        for (int h = w; h < NHEAD; h += 6) {
            float m = -1e30f;
            for (int i = lane; i < cnt; i += 32)
                m = fmaxf(m, g_logits[g_segEdges[base + i] * NHEAD + h]);
#pragma unroll
            for (int off = 16; off; off >>= 1)
                m = fmaxf(m, __shfl_xor_sync(0xffffffffu, m, off));
            float ssum = 0.f;
            for (int i = lane; i < cnt; i += 32)
                ssum += __expf(g_logits[g_segEdges[base + i] * NHEAD + h] - m);
#pragma unroll
            for (int off = 16; off; off >>= 1)
                ssum += __shfl_xor_sync(0xffffffffu, ssum, off);
            if (lane == 0) { shm[h] = m; shinv[h] = 1.0f / ssum; }
        }
        __syncthreads();
        for (int c0 = 0; c0 < cnt; c0 += 32) {
            int nc = min(32, cnt - c0);
            for (int idx = tid; idx < nc * NHEAD; idx += 192) {
                int j = idx / NHEAD, h = idx - NHEAD * j;
                int e = g_segEdges[base + c0 + j];
                ps[j * NHEAD + h] = __expf(g_logits[e * NHEAD + h] - shm[h]) * shinv[h];
            }
            if (tid < nc) tnb[tid] = EI[2 * E_TOT + g_segEdges[base + c0 + tid]];
            __syncthreads();
            for (int j = 0; j < nc; j++) {
                float p = ps[j * NHEAD + h0];
                float4 v = *(const float4*)&g_V[(bb * 512 + tnb[j]) * HIDC + col];
                acc.x += p * v.x; acc.y += p * v.y; acc.z += p * v.z; acc.w += p * v.w;
            }
            __syncthreads();
        }
    }
    *(float4*)&out[s * HIDC + col] = acc;
}

// ---------------- launch ----------------
extern "C" void kernel_launch(void* const* d_in, const int* in_sizes, int n_in,
                              void* d_out, int out_size)
{
    const float* X   = (const float*)d_in[0];
    const int*   EI  = (const int*)  d_in[1];
    const float* Wq  = (const float*)d_in[3];
    const float* bq  = (const float*)d_in[4];
    const float* Wk  = (const float*)d_in[5];
    const float* bk  = (const float*)d_in[6];
    const float* Wv  = (const float*)d_in[7];
    const float* bv  = (const float*)d_in[8];
    const float* rel = (const float*)d_in[9];
    float* out = (float*)d_out;

    cudaFuncSetAttribute(logits_mma,
                         cudaFuncAttributeMaxDynamicSharedMemorySize, LOG_SMEM);

    prep_kernel<<<PREP_BLOCKS, PREP_THREADS>>>(EI);
    qkv_gemm_tc<<<dim3(2048 / 128, 768 / 64, 3), 256>>>(X, Wq, bq, Wk, bk, Wv, bv);
    logits_mma<<<dim3(NRELC, LOG_NCH), 192, LOG_SMEM>>>(rel, EI);
    agg_kernel<<<NSEG, 192>>>(EI, out);
}

// round 14
// speedup vs baseline: 1.5108x; 1.5108x over previous
#include <cuda_runtime.h>
#include <math.h>

#define E_TOT 65536
#define NRELC 64
#define NSEG  2048      // B*N = 4*512
#define HIDC  768
#define NHEAD 12
#define DHC   64

// ---------------- scratch ----------------
__device__ float g_Q[NSEG * HIDC];
__device__ float g_K[NSEG * HIDC];
__device__ float g_V[NSEG * HIDC];
__device__ float g_logitsSeg[E_TOT * NHEAD];   // logits in segment-CSR order
__device__ int   g_relCount[NRELC];
__device__ int   g_relOff[NRELC + 1];
__device__ int   g_relCur[NRELC];
__device__ int   g_segCount[NSEG];
__device__ int   g_segOff[NSEG + 1];
__device__ int   g_segCur[NSEG];
__device__ int   g_relQrow[E_TOT];   // per rel-CSR pos: Q row index (= segment id)
__device__ int   g_relKrow[E_TOT];   // per rel-CSR pos: K/V row index (b*512+tn)
__device__ int   g_relSlot[E_TOT];   // per rel-CSR pos: segment-CSR slot
__device__ int   g_segVrow[E_TOT];   // per seg-CSR slot: V row index

// generational grid barrier state (monotonic across graph replays)
__device__ unsigned g_ticket;
__device__ unsigned g_release;

#define PREP_BLOCKS 128
#define PREP_THREADS 512

__device__ __forceinline__ void grid_bar() {
    __syncthreads();
    if (threadIdx.x == 0) {
        __threadfence();
        unsigned t = atomicAdd(&g_ticket, 1u);
        unsigned gen = t / PREP_BLOCKS;
        if ((t % PREP_BLOCKS) == PREP_BLOCKS - 1)
            atomicAdd(&g_release, 1u);
        while (*(volatile unsigned*)&g_release <= gen) { }
        __threadfence();
    }
    __syncthreads();
}

// ---------------- helpers ----------------
__device__ __forceinline__ unsigned f2tf32(float x) {
    unsigned u;
    asm("cvt.rna.tf32.f32 %0, %1;" : "=r"(u) : "f"(x));
    return u;
}

__device__ __forceinline__ void mma_tf32(float* d, const unsigned* a, const unsigned* b) {
    asm volatile(
        "mma.sync.aligned.m16n8k8.row.col.f32.tf32.tf32.f32 "
        "{%0,%1,%2,%3},{%4,%5,%6,%7},{%8,%9},{%0,%1,%2,%3};\n"
        : "+f"(d[0]), "+f"(d[1]), "+f"(d[2]), "+f"(d[3])
        : "r"(a[0]), "r"(a[1]), "r"(a[2]), "r"(a[3]), "r"(b[0]), "r"(b[1]));
}

// ---------------- fused prep: zero -> count -> scan -> scatter ----------------
__global__ __launch_bounds__(PREP_THREADS) void prep_kernel(const int* __restrict__ EI)
{
    __shared__ int hrel[NRELC];
    __shared__ int hbase[NRELC];
    __shared__ int sh2[PREP_THREADS];

    int tid = threadIdx.x, bid = blockIdx.x;
    int e = bid * PREP_THREADS + tid;

    if (bid == 0 && tid < NRELC) { g_relCount[tid] = 0; g_relCur[tid] = 0; }
    if (bid < 4) { g_segCount[bid * 512 + tid] = 0; g_segCur[bid * 512 + tid] = 0; }
    grid_bar();

    if (tid < NRELC) hrel[tid] = 0;
    __syncthreads();
    int b  = EI[e];
    int hn = EI[E_TOT + e];
    int tn = EI[2 * E_TOT + e];
    int r  = EI[3 * E_TOT + e];
    int s  = b * 512 + hn;
    int kr = b * 512 + tn;
    atomicAdd(&hrel[r], 1);
    atomicAdd(&g_segCount[s], 1);
    __syncthreads();
    if (tid < NRELC && hrel[tid] != 0) atomicAdd(&g_relCount[tid], hrel[tid]);
    grid_bar();

    if (bid == 0) {
        int a0 = g_segCount[tid * 4 + 0], a1 = g_segCount[tid * 4 + 1];
        int a2 = g_segCount[tid * 4 + 2], a3 = g_segCount[tid * 4 + 3];
        int sum = a0 + a1 + a2 + a3;
        sh2[tid] = sum;
        __syncthreads();
        for (int off = 1; off < PREP_THREADS; off <<= 1) {
            int v = (tid >= off) ? sh2[tid - off] : 0;
            __syncthreads();
            sh2[tid] += v;
            __syncthreads();
        }
        int excl = sh2[tid] - sum;
        g_segOff[tid * 4 + 0] = excl;
        g_segOff[tid * 4 + 1] = excl + a0;
        g_segOff[tid * 4 + 2] = excl + a0 + a1;
        g_segOff[tid * 4 + 3] = excl + a0 + a1 + a2;
        if (tid == PREP_THREADS - 1) g_segOff[NSEG] = sh2[tid];
        if (tid == 0) {
            int acc = 0;
            for (int i = 0; i < NRELC; i++) { g_relOff[i] = acc; acc += g_relCount[i]; }
            g_relOff[NRELC] = acc;
        }
    }
    grid_bar();

    if (tid < NRELC) hrel[tid] = 0;
    __syncthreads();
    int lrank = atomicAdd(&hrel[r], 1);
    __syncthreads();
    if (tid < NRELC) {
        int c = hrel[tid];
        hbase[tid] = c ? atomicAdd(&g_relCur[tid], c) : 0;
    }
    __syncthreads();
    int q = atomicAdd(&g_segCur[s], 1);
    int slot = g_segOff[s] + q;
    int p = g_relOff[r] + hbase[r] + lrank;
    g_relQrow[p] = s;
    g_relKrow[p] = kr;
    g_relSlot[p] = slot;
    g_segVrow[slot] = kr;
}

// ---------------- QKV GEMM via tf32 tensor MMA (128x64 tile) ----------------
__global__ __launch_bounds__(256) void qkv_gemm_tc(
    const float* __restrict__ X,
    const float* __restrict__ Wq, const float* __restrict__ bq,
    const float* __restrict__ Wk, const float* __restrict__ bk,
    const float* __restrict__ Wv, const float* __restrict__ bv)
{
    const float* W; const float* bias; float* out;
    if (blockIdx.z == 0)      { W = Wq; bias = bq; out = g_Q; }
    else if (blockIdx.z == 1) { W = Wk; bias = bk; out = g_K; }
    else                      { W = Wv; bias = bv; out = g_V; }

    __shared__ unsigned As[32 * 132];
    __shared__ unsigned Bs[32 * 68];

    int tid = threadIdx.x;
    int lane = tid & 31, w = tid >> 5;
    int wm = w >> 1, wn = w & 1;
    int m0 = blockIdx.x * 128, n0 = blockIdx.y * 64;

    float acc[2][4][4];
#pragma unroll
    for (int i = 0; i < 2; i++)
#pragma unroll
        for (int j = 0; j < 4; j++)
#pragma unroll
            for (int k = 0; k < 4; k++) acc[i][j][k] = 0.f;

    float4 aR[4], bR[2];

#pragma unroll
    for (int j = 0; j < 4; j++) {
        int f4 = tid + j * 256;
        int row = f4 >> 3, c = f4 & 7;
        aR[j] = *(const float4*)&X[(m0 + row) * HIDC + c * 4];
    }
#pragma unroll
    for (int j = 0; j < 2; j++) {
        int f4 = tid + j * 256;
        int n = f4 >> 3, c = f4 & 7;
        bR[j] = *(const float4*)&W[(n0 + n) * HIDC + c * 4];
    }

    for (int kc = 0; kc < 24; kc++) {
#pragma unroll
        for (int j = 0; j < 4; j++) {
            int f4 = tid + j * 256;
            int row = f4 >> 3, c = f4 & 7;
            int sm = (row >> 4) * 4 + (c >> 1);
            unsigned* p = &As[(sm * 33 + (c & 1) * 16 + (row & 15)) * 4];
            *(uint4*)p = make_uint4(f2tf32(aR[j].x), f2tf32(aR[j].y),
                                    f2tf32(aR[j].z), f2tf32(aR[j].w));
        }
#pragma unroll
        for (int j = 0; j < 2; j++) {
            int f4 = tid + j * 256;
            int n = f4 >> 3, c = f4 & 7;
            int sub = (n >> 3) * 4 + (c >> 1);
            unsigned* p = &Bs[(sub * 17 + (c & 1) * 8 + (n & 7)) * 4];
            *(uint4*)p = make_uint4(f2tf32(bR[j].x), f2tf32(bR[j].y),
                                    f2tf32(bR[j].z), f2tf32(bR[j].w));
        }
        __syncthreads();

        if (kc < 23) {
            int k0 = (kc + 1) * 32;
#pragma unroll
            for (int j = 0; j < 4; j++) {
                int f4 = tid + j * 256;
                int row = f4 >> 3, c = f4 & 7;
                aR[j] = *(const float4*)&X[(m0 + row) * HIDC + k0 + c * 4];
            }
#pragma unroll
            for (int j = 0; j < 2; j++) {
                int f4 = tid + j * 256;
                int n = f4 >> 3, c = f4 & 7;
                bR[j] = *(const float4*)&W[(n0 + n) * HIDC + k0 + c * 4];
            }
        }

#pragma unroll
        for (int ks = 0; ks < 4; ks++) {
            unsigned af[2][4];
#pragma unroll
            for (int mi = 0; mi < 2; mi++) {
                int ab = ((wm * 2 + mi) * 4 + ks) * 132 + lane;
                af[mi][0] = As[ab];      af[mi][1] = As[ab + 32];
                af[mi][2] = As[ab + 64]; af[mi][3] = As[ab + 96];
            }
#pragma unroll
            for (int nt = 0; nt < 4; nt++) {
                unsigned bf[2];
                int bb = ((wn * 4 + nt) * 4 + ks) * 68 + lane;
                bf[0] = Bs[bb]; bf[1] = Bs[bb + 32];
#pragma unroll
                for (int mi = 0; mi < 2; mi++)
                    mma_tf32(acc[mi][nt], af[mi], bf);
            }
        }
        __syncthreads();
    }

    int g = lane >> 2, t = lane & 3;
#pragma unroll
    for (int mi = 0; mi < 2; mi++) {
        int r0 = m0 + wm * 32 + mi * 16 + g;
#pragma unroll
        for (int nt = 0; nt < 4; nt++) {
            int col = n0 + wn * 32 + nt * 8 + t * 2;
            float b0 = __ldg(&bias[col]), b1 = __ldg(&bias[col + 1]);
            float2 v0 = make_float2(acc[mi][nt][0] + b0, acc[mi][nt][1] + b1);
            *(float2*)&out[r0 * HIDC + col] = v0;
            float2 v1 = make_float2(acc[mi][nt][2] + b0, acc[mi][nt][3] + b1);
            *(float2*)&out[(r0 + 8) * HIDC + col] = v1;
        }
    }
}

// ---------------- edge logits via tf32 MMA (LTE=8, K direct from L2) ----------------
// writes logits directly in segment-CSR order via precomputed slots
#define LTE 8
#define LOG_NCH 32
#define QS_FLOATS (48 * 132)               // 6336
#define RS_FLOATS (64 * 68)                // 4352
#define LOG_SMEM ((QS_FLOATS + RS_FLOATS) * 4)

__global__ __launch_bounds__(192) void logits_mma(const float* __restrict__ rel_emb)
{
    extern __shared__ float smx[];
    unsigned* Qs = (unsigned*)smx;
    unsigned* Rs = (unsigned*)(smx + QS_FLOATS);
    __shared__ int slots[LTE], qrow[LTE], krow[LTE];

    int r = blockIdx.x;
    int cnt = g_relCount[r];
    if ((int)(blockIdx.y * LTE) >= cnt) return;
    int base = g_relOff[r];
    int tid = threadIdx.x, lane = tid & 31, w = tid >> 5;

    // stage R once: fragment-major tf32 (B-operand layout)
    const float* Rg = rel_emb + r * 4096;
    for (int idx = tid; idx < 1024; idx += 192) {
        float4 v = *(const float4*)&Rg[idx * 4];
        int d = idx >> 4, kc0 = (idx & 15) * 4;
        int sub = (d >> 3) * 8 + (kc0 >> 3);
        int p0 = sub * 68 + ((d & 7) >> 2) * 32 + (d & 3);
        int nb = kc0 & 7;
        Rs[p0 + (nb + 0) * 4] = f2tf32(v.x);
        Rs[p0 + (nb + 1) * 4] = f2tf32(v.y);
        Rs[p0 + (nb + 2) * 4] = f2tf32(v.z);
        Rs[p0 + (nb + 3) * 4] = f2tf32(v.w);
    }

    int g = lane >> 2, t = lane & 3;
    int m0r = w * 16 + g, m1r = m0r + 8;
    int i0 = m0r / 12, h0 = m0r - i0 * 12;
    int i1 = m1r / 12, h1 = m1r - i1 * 12;

    for (int c = blockIdx.y * LTE; c < cnt; c += LOG_NCH * LTE) {
        __syncthreads();
        if (tid < LTE) {
            int il = min(c + tid, cnt - 1);
            qrow[tid]  = g_relQrow[base + il] * HIDC;
            krow[tid]  = g_relKrow[base + il] * HIDC;
            slots[tid] = g_relSlot[base + il];
        }
        __syncthreads();

        // stage Q (fragment-major tf32): 1536 float4, 8 per thread
#pragma unroll
        for (int j = 0; j < 8; j++) {
            int f4 = tid + j * 192;
            int m = f4 >> 4, dc = f4 & 15;
            int i = m / 12, h = m - i * 12;
            float4 v = *(const float4*)&g_Q[qrow[i] + h * 64 + dc * 4];
            int sm = (m >> 4) * 8 + (dc >> 1);
            unsigned* p = &Qs[(sm * 33 + (dc & 1) * 16 + (m & 15)) * 4];
            *(uint4*)p = make_uint4(f2tf32(v.x), f2tf32(v.y), f2tf32(v.z), f2tf32(v.w));
        }
        __syncthreads();

        // MMA: warp w owns m-tile w (16 rows x 64 cols)
        float acc[8][4];
#pragma unroll
        for (int nt = 0; nt < 8; nt++)
#pragma unroll
            for (int k = 0; k < 4; k++) acc[nt][k] = 0.f;

#pragma unroll
        for (int ks = 0; ks < 8; ks++) {
            unsigned af[4];
            int ab = (w * 8 + ks) * 132 + lane;
            af[0] = Qs[ab];      af[1] = Qs[ab + 32];
            af[2] = Qs[ab + 64]; af[3] = Qs[ab + 96];
#pragma unroll
            for (int nt = 0; nt < 8; nt++) {
                unsigned bf[2];
                int bb = (ks * 8 + nt) * 68 + lane;
                bf[0] = Rs[bb]; bf[1] = Rs[bb + 32];
                mma_tf32(acc[nt], af, bf);
            }
        }

        // epilogue: dot Qp rows with K rows straight from L2
        float p0 = 0.f, p1 = 0.f;
        const float* k0p = &g_K[krow[i0] + h0 * 64];
        const float* k1p = &g_K[krow[i1] + h1 * 64];
#pragma unroll
        for (int nt = 0; nt < 8; nt++) {
            int col = nt * 8 + t * 2;
            float2 ka = *(const float2*)&k0p[col];
            float2 kb = *(const float2*)&k1p[col];
            p0 += acc[nt][0] * ka.x + acc[nt][1] * ka.y;
            p1 += acc[nt][2] * kb.x + acc[nt][3] * kb.y;
        }
        p0 += __shfl_xor_sync(0xffffffffu, p0, 1);
        p0 += __shfl_xor_sync(0xffffffffu, p0, 2);
        p1 += __shfl_xor_sync(0xffffffffu, p1, 1);
        p1 += __shfl_xor_sync(0xffffffffu, p1, 2);
        if (t == 0) {
            if (c + i0 < cnt) g_logitsSeg[slots[i0] * NHEAD + h0] = p0 * 0.125f;
            if (c + i1 < cnt) g_logitsSeg[slots[i1] * NHEAD + h1] = p1 * 0.125f;
        }
    }
}

// ---------------- per-segment softmax + V aggregation (fully streaming inputs) ----------------
#define AGG_CAP 128
__global__ __launch_bounds__(192) void agg_kernel(float* __restrict__ out)
{
    __shared__ float lg[AGG_CAP * 13];
    __shared__ int   vrow2[AGG_CAP];
    __shared__ float shm[NHEAD], shinv[NHEAD];
    __shared__ float ps[32 * NHEAD];
    __shared__ int   vrow1[32];

    int s = blockIdx.x;
    int base = g_segOff[s];
    int cnt  = g_segOff[s + 1] - base;
    int tid = threadIdx.x, lane = tid & 31, w = tid >> 5;
    int col = tid * 4;        // 192 threads x 4 floats = 768
    int h0 = tid >> 4;        // col >> 6

    float4 acc = make_float4(0.f, 0.f, 0.f, 0.f);

    if (cnt == 0) {
        *(float4*)&out[s * HIDC + col] = acc;
        return;
    }

    if (cnt <= AGG_CAP) {
        // contiguous float4 loads of segment logits (base*12 floats is 16B aligned)
        const float4* Lg4 = (const float4*)(g_logitsSeg + base * NHEAD);
        for (int idx4 = tid; idx4 < cnt * 3; idx4 += 192) {
            float4 v = Lg4[idx4];
            int j = idx4 / 3;
            int hh = (idx4 - 3 * j) * 4;
            float* dst = &lg[j * 13 + hh];
            dst[0] = v.x; dst[1] = v.y; dst[2] = v.z; dst[3] = v.w;
        }
        for (int idx = tid; idx < cnt; idx += 192)
            vrow2[idx] = g_segVrow[base + idx] * HIDC;
        __syncthreads();
        for (int h = w; h < NHEAD; h += 6) {
            float m = -1e30f;
            for (int i = lane; i < cnt; i += 32) m = fmaxf(m, lg[i * 13 + h]);
#pragma unroll
            for (int off = 16; off; off >>= 1)
                m = fmaxf(m, __shfl_xor_sync(0xffffffffu, m, off));
            float ss = 0.f;
            for (int i = lane; i < cnt; i += 32) ss += __expf(lg[i * 13 + h] - m);
#pragma unroll
            for (int off = 16; off; off >>= 1)
                ss += __shfl_xor_sync(0xffffffffu, ss, off);
            if (lane == 0) { shm[h] = m; shinv[h] = 1.0f / ss; }
        }
        __syncthreads();
        for (int idx = tid; idx < cnt * NHEAD; idx += 192) {
            int j = idx / NHEAD, h = idx - NHEAD * j;
            lg[j * 13 + h] = __expf(lg[j * 13 + h] - shm[h]) * shinv[h];
        }
        __syncthreads();
        int j = 0;
        for (; j + 4 <= cnt; j += 4) {
            float p0 = lg[(j + 0) * 13 + h0];
            float p1 = lg[(j + 1) * 13 + h0];
            float p2 = lg[(j + 2) * 13 + h0];
            float p3 = lg[(j + 3) * 13 + h0];
            float4 v0 = *(const float4*)&g_V[vrow2[j + 0] + col];
            float4 v1 = *(const float4*)&g_V[vrow2[j + 1] + col];
            float4 v2 = *(const float4*)&g_V[vrow2[j + 2] + col];
            float4 v3 = *(const float4*)&g_V[vrow2[j + 3] + col];
            acc.x += p0 * v0.x + p1 * v1.x + p2 * v2.x + p3 * v3.x;
            acc.y += p0 * v0.y + p1 * v1.y + p2 * v2.y + p3 * v3.y;
            acc.z += p0 * v0.z + p1 * v1.z + p2 * v2.z + p3 * v3.z;
            acc.w += p0 * v0.w + p1 * v1.w + p2 * v2.w + p3 * v3.w;
        }
        for (; j < cnt; j++) {
            float p = lg[j * 13 + h0];
            float4 v = *(const float4*)&g_V[vrow2[j] + col];
            acc.x += p * v.x; acc.y += p * v.y; acc.z += p * v.z; acc.w += p * v.w;
        }
    } else {
        // streaming fallback (contiguous logits, so this is cheap too)
        for (int h = w; h < NHEAD; h += 6) {
            float m = -1e30f;
            for (int i = lane; i < cnt; i += 32)
                m = fmaxf(m, g_logitsSeg[(base + i) * NHEAD + h]);
#pragma unroll
            for (int off = 16; off; off >>= 1)
                m = fmaxf(m, __shfl_xor_sync(0xffffffffu, m, off));
            float ssum = 0.f;
            for (int i = lane; i < cnt; i += 32)
                ssum += __expf(g_logitsSeg[(base + i) * NHEAD + h] - m);
#pragma unroll
            for (int off = 16; off; off >>= 1)
                ssum += __shfl_xor_sync(0xffffffffu, ssum, off);
            if (lane == 0) { shm[h] = m; shinv[h] = 1.0f / ssum; }
        }
        __syncthreads();
        for (int c0 = 0; c0 < cnt; c0 += 32) {
            int nc = min(32, cnt - c0);
            for (int idx = tid; idx < nc * NHEAD; idx += 192) {
                int j = idx / NHEAD, h = idx - NHEAD * j;
                ps[j * NHEAD + h] =
                    __expf(g_logitsSeg[(base + c0 + j) * NHEAD + h] - shm[h]) * shinv[h];
            }
            if (tid < nc) vrow1[tid] = g_segVrow[base + c0 + tid] * HIDC;
            __syncthreads();
            for (int j = 0; j < nc; j++) {
                float p = ps[j * NHEAD + h0];
                float4 v = *(const float4*)&g_V[vrow1[j] + col];
                acc.x += p * v.x; acc.y += p * v.y; acc.z += p * v.z; acc.w += p * v.w;
            }
            __syncthreads();
        }
    }
    *(float4*)&out[s * HIDC + col] = acc;
}

// ---------------- launch ----------------
extern "C" void kernel_launch(void* const* d_in, const int* in_sizes, int n_in,
                              void* d_out, int out_size)
{
    const float* X   = (const float*)d_in[0];
    const int*   EI  = (const int*)  d_in[1];
    const float* Wq  = (const float*)d_in[3];
    const float* bq  = (const float*)d_in[4];
    const float* Wk  = (const float*)d_in[5];
    const float* bk  = (const float*)d_in[6];
    const float* Wv  = (const float*)d_in[7];
    const float* bv  = (const float*)d_in[8];
    const float* rel = (const float*)d_in[9];
    float* out = (float*)d_out;

    cudaFuncSetAttribute(logits_mma,
                         cudaFuncAttributeMaxDynamicSharedMemorySize, LOG_SMEM);

    prep_kernel<<<PREP_BLOCKS, PREP_THREADS>>>(EI);
    qkv_gemm_tc<<<dim3(2048 / 128, 768 / 64, 3), 256>>>(X, Wq, bq, Wk, bk, Wv, bv);
    logits_mma<<<dim3(NRELC, LOG_NCH), 192, LOG_SMEM>>>(rel);
    agg_kernel<<<NSEG, 192>>>(out);
}